// round 1
// baseline (speedup 1.0000x reference)
#include <cuda_runtime.h>

// FullAttention with causal + log-sparse mask, B=4, L=2048, H=8, E=D=64, fp32.
// Mask reduces to: query l attends keys at l - d for d in OFF (17 offsets), d <= l.
// Layout: Q,K,V,O all [B, L, H, 64] row-major (O matches 'blhd').

constexpr int Bc = 4, Lc = 2048, Hc = 8;
constexpr int N_OFF = 17;
constexpr float SCALE = 0.125f; // 1/sqrt(64)

// queries per warp = 2 (half-warp each), 8 warps/CTA -> 16 queries per CTA
constexpr int WARPS = 8;
constexpr int QPB = WARPS * 2;              // 16
constexpr int CHUNKS = Lc / QPB;            // 128

__global__ __launch_bounds__(256) void sparse_attn_kernel(
    const float* __restrict__ Q,
    const float* __restrict__ K,
    const float* __restrict__ V,
    float* __restrict__ O)
{
    constexpr int OFF[N_OFF] = {0,1,2,3,4,5,6,7,9,13,21,37,69,133,261,517,1029};

    const int tid  = threadIdx.x;
    const int warp = tid >> 5;
    const int lane = tid & 31;
    const int half = lane >> 4;      // 0 or 1: which query this half-warp owns
    const int sub  = lane & 15;      // lane within half-warp

    const int c      = blockIdx.x;
    const int bh     = c >> 7;       // c / CHUNKS (CHUNKS = 128)
    const int lchunk = c & (CHUNKS - 1);
    const int l      = lchunk * QPB + warp * 2 + half;
    const int b      = bh >> 3;      // bh / H
    const int h      = bh & 7;       // bh % H

    // element index of this lane's float4 within the [B,L,H,64] tensor
    const int row = ((b * Lc + l) * Hc + h) * 64 + sub * 4;
    const int rowStride = Hc * 64;   // one l step = 512 elements

    const float4 q = *reinterpret_cast<const float4*>(Q + row);

    float s[N_OFF];

    #pragma unroll
    for (int t = 0; t < N_OFF; t++) {
        const int d = OFF[t];
        const bool valid = (d <= l);
        const int krow = valid ? (row - d * rowStride) : row; // clamped in-bounds
        const float4 k = *reinterpret_cast<const float4*>(K + krow);
        float p = q.x * k.x;
        p = fmaf(q.y, k.y, p);
        p = fmaf(q.z, k.z, p);
        p = fmaf(q.w, k.w, p);
        // butterfly reduce within the 16-lane half-warp
        p += __shfl_xor_sync(0xffffffffu, p, 8);
        p += __shfl_xor_sync(0xffffffffu, p, 4);
        p += __shfl_xor_sync(0xffffffffu, p, 2);
        p += __shfl_xor_sync(0xffffffffu, p, 1);
        s[t] = valid ? p * SCALE : -INFINITY;
    }

    // softmax over the <=17 scores (every lane holds the full reduced values)
    float m = s[0];
    #pragma unroll
    for (int t = 1; t < N_OFF; t++) m = fmaxf(m, s[t]);

    float sum = 0.f;
    #pragma unroll
    for (int t = 0; t < N_OFF; t++) {
        s[t] = __expf(s[t] - m);   // -inf -> 0
        sum += s[t];
    }
    const float inv = 1.f / sum;

    float4 acc = make_float4(0.f, 0.f, 0.f, 0.f);
    #pragma unroll
    for (int t = 0; t < N_OFF; t++) {
        const int d = OFF[t];
        const int vrow = (d <= l) ? (row - d * rowStride) : row; // weight is 0 when invalid
        const float4 v = *reinterpret_cast<const float4*>(V + vrow);
        const float p = s[t];
        acc.x = fmaf(p, v.x, acc.x);
        acc.y = fmaf(p, v.y, acc.y);
        acc.z = fmaf(p, v.z, acc.z);
        acc.w = fmaf(p, v.w, acc.w);
    }
    acc.x *= inv; acc.y *= inv; acc.z *= inv; acc.w *= inv;

    *reinterpret_cast<float4*>(O + row) = acc;
}

extern "C" void kernel_launch(void* const* d_in, const int* in_sizes, int n_in,
                              void* d_out, int out_size)
{
    const float* Q = (const float*)d_in[0];
    const float* K = (const float*)d_in[1];
    const float* V = (const float*)d_in[2];
    float* O = (float*)d_out;

    const int nblocks = Bc * Hc * CHUNKS; // 4*8*128 = 4096
    sparse_attn_kernel<<<nblocks, 256>>>(Q, K, V, O);
}

// round 2
// speedup vs baseline: 1.2452x; 1.2452x over previous
#include <cuda_runtime.h>

// Log-sparse causal attention, B=4, L=2048, H=8, E=D=64, fp32.
// Query l attends keys l-d for d in OFF (17 offsets), d <= l.
// Half-warp (16 lanes) processes QG=4 consecutive queries, sharing K/V row
// loads across the group (45 distinct rows instead of 68).
// Scores reduced with a transpose-reduce: lane t ends up holding score t.

constexpr int Bc = 4, Lc = 2048, Hc = 8;
constexpr float SCALE = 0.125f;      // 1/sqrt(64)
constexpr int ROWSTR = Hc * 64;      // 512 elements per l-step

// 17 allowed offsets
__device__ constexpr int NOFF = 17;

// 45 distinct relative rows e (row = l0 - e) covering all (j in 0..3, d in OFF)
__device__ constexpr int EREL[45] = {
    -3,-2,-1,0,1,2,3,4,5,6,7,8,9,10,11,12,13,
    18,19,20,21, 34,35,36,37, 66,67,68,69,
    130,131,132,133, 258,259,260,261, 514,515,516,517,
    1026,1027,1028,1029
};

// TIDX[ei][j] = score-slot t (index into OFF) for query l0+j at row l0-EREL[ei], or -1
__device__ constexpr int TIDX[45][4] = {
    {-1,-1,-1, 0}, {-1,-1, 0, 1}, {-1, 0, 1, 2}, { 0, 1, 2, 3},
    { 1, 2, 3, 4}, { 2, 3, 4, 5}, { 3, 4, 5, 6}, { 4, 5, 6, 7},
    { 5, 6, 7,-1}, { 6, 7,-1, 8}, { 7,-1, 8,-1}, {-1, 8,-1,-1},
    { 8,-1,-1,-1}, {-1,-1,-1, 9}, {-1,-1, 9,-1}, {-1, 9,-1,-1},
    { 9,-1,-1,-1},
    {-1,-1,-1,10}, {-1,-1,10,-1}, {-1,10,-1,-1}, {10,-1,-1,-1},
    {-1,-1,-1,11}, {-1,-1,11,-1}, {-1,11,-1,-1}, {11,-1,-1,-1},
    {-1,-1,-1,12}, {-1,-1,12,-1}, {-1,12,-1,-1}, {12,-1,-1,-1},
    {-1,-1,-1,13}, {-1,-1,13,-1}, {-1,13,-1,-1}, {13,-1,-1,-1},
    {-1,-1,-1,14}, {-1,-1,14,-1}, {-1,14,-1,-1}, {14,-1,-1,-1},
    {-1,-1,-1,15}, {-1,-1,15,-1}, {-1,15,-1,-1}, {15,-1,-1,-1},
    {-1,-1,-1,16}, {-1,-1,16,-1}, {-1,16,-1,-1}, {16,-1,-1,-1}
};

// OFF[u] for u in 0..15 computed arithmetically: u<8 -> u, else 2^(u-6)+5
__device__ __forceinline__ int off_of_lane(int u) {
    return (u < 8) ? u : ((1 << (u - 6)) + 5);
}

// Transpose-reduce: 16 per-lane partials -> lane u (within 16-lane half)
// holds the full 16-lane sum of value u. 15 SHFLs.
__device__ __forceinline__ float txreduce16(const float* v, int lane) {
    const unsigned FULL = 0xffffffffu;
    const bool b8 = (lane & 8) != 0;
    float w[8];
    #pragma unroll
    for (int i = 0; i < 8; i++) {
        float own = b8 ? v[i + 8] : v[i];
        float oth = b8 ? v[i] : v[i + 8];
        w[i] = own + __shfl_xor_sync(FULL, oth, 8);
    }
    const bool b4 = (lane & 4) != 0;
    float x[4];
    #pragma unroll
    for (int i = 0; i < 4; i++) {
        float own = b4 ? w[i + 4] : w[i];
        float oth = b4 ? w[i] : w[i + 4];
        x[i] = own + __shfl_xor_sync(FULL, oth, 4);
    }
    const bool b2 = (lane & 2) != 0;
    float y[2];
    #pragma unroll
    for (int i = 0; i < 2; i++) {
        float own = b2 ? y[0] : y[0]; // placeholder, replaced below
        float oth;
        own = b2 ? x[i + 2] : x[i];
        oth = b2 ? x[i] : x[i + 2];
        y[i] = own + __shfl_xor_sync(FULL, oth, 2);
    }
    const bool b1 = (lane & 1) != 0;
    float own = b1 ? y[1] : y[0];
    float oth = b1 ? y[0] : y[1];
    return own + __shfl_xor_sync(FULL, oth, 1);
}

__global__ __launch_bounds__(128) void sparse_attn_qg4(
    const float* __restrict__ Q,
    const float* __restrict__ K,
    const float* __restrict__ V,
    float* __restrict__ O)
{
    const unsigned FULL = 0xffffffffu;
    const int tid  = threadIdx.x;
    const int warp = tid >> 5;
    const int lane = tid & 31;
    const int half = lane >> 4;
    const int sub  = lane & 15;      // dim slice: floats [4*sub, 4*sub+4)

    // CTA = 32 consecutive queries of one (b,h). grid = 4*8*64 = 2048
    const int cta   = blockIdx.x;
    const int chunk = cta & 63;
    const int bh    = cta >> 6;
    const int h     = bh & 7;
    const int b     = bh >> 3;

    const int l0 = chunk * 32 + warp * 8 + half * 4;   // first of 4 queries

    const int rbase = ((b * Lc + l0) * Hc + h) * 64 + sub * 4;

    // load the 4 query rows
    float4 q0 = *reinterpret_cast<const float4*>(Q + rbase);
    float4 q1 = *reinterpret_cast<const float4*>(Q + rbase + ROWSTR);
    float4 q2 = *reinterpret_cast<const float4*>(Q + rbase + 2 * ROWSTR);
    float4 q3 = *reinterpret_cast<const float4*>(Q + rbase + 3 * ROWSTR);

    float s[4][17];

    // ---------- Phase 1: partial scores, shared K row loads ----------
    #pragma unroll
    for (int ei = 0; ei < 45; ei++) {
        const int e = EREL[ei];
        const bool ok = (l0 >= e);
        const int addr = ok ? (rbase - e * ROWSTR) : rbase;
        const float4 k = *reinterpret_cast<const float4*>(K + addr);
        #pragma unroll
        for (int j = 0; j < 4; j++) {
            const int t = TIDX[ei][j];
            if (t >= 0) {
                const float4 qq = (j == 0) ? q0 : (j == 1) ? q1 : (j == 2) ? q2 : q3;
                float p = qq.x * k.x;
                p = fmaf(qq.y, k.y, p);
                p = fmaf(qq.z, k.z, p);
                p = fmaf(qq.w, k.w, p);
                s[j][t] = p;
            }
        }
    }

    // ---------- Phase 2: softmax per query ----------
    const int u = sub;                       // lane within half
    const int myoff = off_of_lane(u);        // OFF[u] for u<16
    float ejr[4], e16r[4], inv[4];

    #pragma unroll
    for (int j = 0; j < 4; j++) {
        float z = txreduce16(&s[j][0], lane);     // lane u holds raw score u
        // 17th score (offset 1029): classic butterfly, replicated
        float s16 = s[j][16];
        s16 += __shfl_xor_sync(FULL, s16, 8);
        s16 += __shfl_xor_sync(FULL, s16, 4);
        s16 += __shfl_xor_sync(FULL, s16, 2);
        s16 += __shfl_xor_sync(FULL, s16, 1);

        const bool valid   = (l0 + j >= myoff);
        const bool valid16 = (l0 + j >= 1029);
        float sc   = valid   ? z   * SCALE : -INFINITY;
        float sc16 = valid16 ? s16 * SCALE : -INFINITY;

        float mm = sc;
        mm = fmaxf(mm, __shfl_xor_sync(FULL, mm, 8));
        mm = fmaxf(mm, __shfl_xor_sync(FULL, mm, 4));
        mm = fmaxf(mm, __shfl_xor_sync(FULL, mm, 2));
        mm = fmaxf(mm, __shfl_xor_sync(FULL, mm, 1));
        mm = fmaxf(mm, sc16);

        float ej  = __expf(sc - mm);               // exp(-inf) -> 0
        float e16 = valid16 ? __expf(sc16 - mm) : 0.f;

        float sm = ej;
        sm += __shfl_xor_sync(FULL, sm, 8);
        sm += __shfl_xor_sync(FULL, sm, 4);
        sm += __shfl_xor_sync(FULL, sm, 2);
        sm += __shfl_xor_sync(FULL, sm, 1);
        sm += e16;

        ejr[j]  = ej;
        e16r[j] = e16;
        inv[j]  = 1.f / sm;
    }

    // ---------- Phase 3: weighted V accumulation, shared V row loads ----------
    float4 a0 = make_float4(0.f, 0.f, 0.f, 0.f);
    float4 a1 = a0, a2 = a0, a3 = a0;
    const int halfbase = lane & 16;

    #pragma unroll
    for (int ei = 0; ei < 45; ei++) {
        const int e = EREL[ei];
        const bool ok = (l0 >= e);
        const int addr = ok ? (rbase - e * ROWSTR) : rbase;
        const float4 v = *reinterpret_cast<const float4*>(V + addr);
        #pragma unroll
        for (int j = 0; j < 4; j++) {
            const int t = TIDX[ei][j];
            if (t >= 0) {
                float w;
                if (t == 16) w = e16r[j];       // replicated
                else         w = __shfl_sync(FULL, ejr[j], halfbase + t);
                // invalid rows have weight exactly 0 -> clamped load is harmless
                float4& a = (j == 0) ? a0 : (j == 1) ? a1 : (j == 2) ? a2 : a3;
                a.x = fmaf(w, v.x, a.x);
                a.y = fmaf(w, v.y, a.y);
                a.z = fmaf(w, v.z, a.z);
                a.w = fmaf(w, v.w, a.w);
            }
        }
    }

    a0.x *= inv[0]; a0.y *= inv[0]; a0.z *= inv[0]; a0.w *= inv[0];
    a1.x *= inv[1]; a1.y *= inv[1]; a1.z *= inv[1]; a1.w *= inv[1];
    a2.x *= inv[2]; a2.y *= inv[2]; a2.z *= inv[2]; a2.w *= inv[2];
    a3.x *= inv[3]; a3.y *= inv[3]; a3.z *= inv[3]; a3.w *= inv[3];

    *reinterpret_cast<float4*>(O + rbase)              = a0;
    *reinterpret_cast<float4*>(O + rbase + ROWSTR)     = a1;
    *reinterpret_cast<float4*>(O + rbase + 2 * ROWSTR) = a2;
    *reinterpret_cast<float4*>(O + rbase + 3 * ROWSTR) = a3;
}

extern "C" void kernel_launch(void* const* d_in, const int* in_sizes, int n_in,
                              void* d_out, int out_size)
{
    const float* Q = (const float*)d_in[0];
    const float* K = (const float*)d_in[1];
    const float* V = (const float*)d_in[2];
    float* O = (float*)d_out;

    const int nblocks = Bc * Hc * (Lc / 32); // 2048
    sparse_attn_qg4<<<nblocks, 128>>>(Q, K, V, O);
}